// round 12
// baseline (speedup 1.0000x reference)
#include <cuda_runtime.h>
#include <math.h>

#define Bc     4
#define Sc     16
#define Dc     1024
#define DNc    2048
#define Kc     8
#define NBc    4
#define VOCABc 151936
#define NBLK   1024
#define NTHR   128

// ---------------- device state (static; no allocation) ----------------
__device__ float g_Vst[2 * NBc * Bc * DNc];   // ping-pong V state [par][blk][b][n]
__device__ float g_u[NBc * Bc * Dc];          // PLIF output-neuron state
__device__ float g_xbuf[2][Bc * Dc];          // ping-pong spike vectors between blocks
__device__ float g_sp[Bc * DNc];              // internal spikes of current block
__device__ float g_frames[Kc * Bc * Dc];      // binary frames for current token
__device__ float g_decoded[Bc * Dc];          // weighted sum of output frames
__device__ float g_hh[Bc * Dc];               // decoded @ dec_W.T (+rmsnorm in place)

// software grid barrier state (self-resetting: count returns to 0, gen monotonic)
__device__ unsigned g_bar_count;
__device__ volatile unsigned g_bar_gen;

// ---------------- helpers ----------------
__device__ __forceinline__ float sigmf_(float a) { return 1.0f / (1.0f + expf(-a)); }
__device__ __forceinline__ float softplusf_(float a) {
    return fmaxf(a, 0.0f) + log1pf(expf(-fabsf(a)));
}
__device__ __forceinline__ float warp_sum(float v) {
    v += __shfl_xor_sync(0xffffffffu, v, 16);
    v += __shfl_xor_sync(0xffffffffu, v, 8);
    v += __shfl_xor_sync(0xffffffffu, v, 4);
    v += __shfl_xor_sync(0xffffffffu, v, 2);
    v += __shfl_xor_sync(0xffffffffu, v, 1);
    return v;
}
__device__ __forceinline__ float dot4(float acc, float4 wv, float4 av) {
    return fmaf(wv.x, av.x, fmaf(wv.y, av.y, fmaf(wv.z, av.z, fmaf(wv.w, av.w, acc))));
}

// Two-variable grid barrier. All 1024 blocks are co-resident
// (launch_bounds(128,8) -> 8 blocks/SM -> capacity 1184 >= 1024).
__device__ __forceinline__ void grid_sync() {
    __syncthreads();
    if (threadIdx.x == 0) {
        __threadfence();                       // release prior writes
        unsigned gen = g_bar_gen;
        if (atomicAdd(&g_bar_count, 1u) == (unsigned)(gridDim.x - 1)) {
            g_bar_count = 0;
            __threadfence();
            g_bar_gen = gen + 1;               // release
        } else {
            while (g_bar_gen == gen) __nanosleep(64);
        }
        __threadfence();                       // acquire
    }
    __syncthreads();
}

// NR output rows x 4 batch operands, 4-way column split across the block's 4 warps.
// STREAM=true  -> weights via __ldcs (evict-first; one-shot stream: blk1, embed)
// STREAM=false -> weights via __ldg  (default; L2-persistent: blk2/enc/dec, ~67MB total)
// Per-accumulator FMA order is IDENTICAL to the validated R10 kernel.
template <int NR, int NF4, bool STREAM>
__device__ __forceinline__ void passN(
    const float* __restrict__ wrow0, int ldw,
    const float* __restrict__ px0, const float* __restrict__ px1,
    const float* __restrict__ px2, const float* __restrict__ px3,
    int warp, int lane, float* acc)
{
    const float4* a0 = (const float4*)px0;
    const float4* a1 = (const float4*)px1;
    const float4* a2 = (const float4*)px2;
    const float4* a3 = (const float4*)px3;
    int cbase = warp * NF4 * 32 + lane;
#pragma unroll
    for (int it = 0; it < NF4; ++it) {
        int idx = cbase + it * 32;
        float4 b0 = __ldg(a0 + idx);
        float4 b1 = __ldg(a1 + idx);
        float4 b2 = __ldg(a2 + idx);
        float4 b3 = __ldg(a3 + idx);
#pragma unroll
        for (int r = 0; r < NR; ++r) {
            const float4* wr = (const float4*)(wrow0 + (size_t)r * ldw);
            float4 q = STREAM ? __ldcs(wr + idx) : __ldg(wr + idx);
            acc[r * 4 + 0] = dot4(acc[r * 4 + 0], q, b0);
            acc[r * 4 + 1] = dot4(acc[r * 4 + 1], q, b1);
            acc[r * 4 + 2] = dot4(acc[r * 4 + 2], q, b2);
            acc[r * 4 + 3] = dot4(acc[r * 4 + 3], q, b3);
        }
    }
}

template <int NA>
__device__ __forceinline__ void reduceN(const float* acc, float (*sh)[4], int warp, int lane) {
#pragma unroll
    for (int i = 0; i < NA; ++i) {
        float v = warp_sum(acc[i]);
        if (lane == 0) sh[i][warp] = v;
    }
}

__device__ __forceinline__ const float* xsel_ptr(int sel) {
    return (sel < Kc) ? (g_frames + (size_t)sel * Bc * Dc) : g_xbuf[sel - Kc];
}

// ---------------- the whole model as ONE persistent kernel ----------------
__global__ void __launch_bounds__(NTHR, 8) snn_mono_kernel(
    const int* __restrict__ tok, const float* __restrict__ embed,
    const float* __restrict__ norm_w,
    const float* __restrict__ encW, const float* __restrict__ encb,
    const float* __restrict__ decW, const float* __restrict__ decb,
    const float* __restrict__ Win, const float* __restrict__ WbX,
    const float* __restrict__ WaX, const float* __restrict__ WtX,
    const float* __restrict__ WbV, const float* __restrict__ WaV,
    const float* __restrict__ WtV,
    const float* __restrict__ b_beta, const float* __restrict__ b_alpha,
    const float* __restrict__ b_th,
    const float* __restrict__ Wgate, const float* __restrict__ Wskip,
    const float* __restrict__ Wout,
    const float* __restrict__ plif_w, const float* __restrict__ out_vth,
    float* __restrict__ out)
{
    const int blk  = blockIdx.x;           // 0..1023
    const int tid  = threadIdx.x;
    const int warp = tid >> 5, lane = tid & 31;
    __shared__ float sh[4][8][4];

    // ---- init state (deterministic every replay) ----
    for (int i = blk * NTHR + tid; i < NBc * Bc * DNc; i += NBLK * NTHR) g_Vst[i] = 0.0f;
    for (int i = blk * NTHR + tid; i < NBc * Bc * Dc;  i += NBLK * NTHR) g_u[i]   = 0.0f;
    grid_sync();

    int par = 0;
    for (int t = 0; t < Sc; ++t) {
        // ================= encoder: 1 row/block =================
        {
            int j = blk;
            const float* e0 = embed + (size_t)__ldg(tok + 0 * Sc + t) * Dc;
            const float* e1 = embed + (size_t)__ldg(tok + 1 * Sc + t) * Dc;
            const float* e2 = embed + (size_t)__ldg(tok + 2 * Sc + t) * Dc;
            const float* e3 = embed + (size_t)__ldg(tok + 3 * Sc + t) * Dc;
            float acc[4];
#pragma unroll
            for (int i = 0; i < 4; ++i) acc[i] = 0.0f;
            passN<1, 2, false>(encW + (size_t)j * Dc, Dc, e0, e1, e2, e3, warp, lane, acc);
            reduceN<4>(acc, sh[0], warp, lane);
            __syncthreads();
            if (tid < 4) {
                int b = tid;
                float s = sh[0][tid][0] + sh[0][tid][1] + sh[0][tid][2] + sh[0][tid][3];
                float res = sigmf_(s + __ldg(encb + j));
#pragma unroll
                for (int k = 0; k < Kc; ++k) {
                    float bit = (res >= 0.5f) ? 1.0f : 0.0f;
                    g_frames[((size_t)k * Bc + b) * Dc + j] = bit;
                    res = (res - 0.5f * bit) * 2.0f;
                }
                g_decoded[b * Dc + j] = 0.0f;
            }
        }
        grid_sync();

        // ================= K frames x NB blocks =================
        for (int k = 0; k < Kc; ++k) {
            int xin = k;                         // frame k feeds block 0
            for (int i = 0; i < NBc; ++i) {
                // ---- blk1: 2 rows/block, fused 7-GEMV + V update + spike ----
                {
                    size_t n0 = (size_t)blk * 2;
                    const float* x  = xsel_ptr(xin);
                    const float* Vi = g_Vst + ((size_t)par * NBc + i) * Bc * DNc;
                    float*       Vo = g_Vst + ((size_t)(par ^ 1) * NBc + i) * Bc * DNc;
                    const float* x0 = x;            const float* x1 = x + Dc;
                    const float* x2 = x + 2 * Dc;   const float* x3 = x + 3 * Dc;
                    const float* v0 = Vi;           const float* v1 = Vi + DNc;
                    const float* v2 = Vi + 2 * DNc; const float* v3 = Vi + 3 * DNc;
                    size_t rX = ((size_t)i * DNc + n0) * Dc;
                    size_t rV = ((size_t)i * DNc + n0) * DNc;
                    float acc[8];
#pragma unroll
                    for (int q = 0; q < 8; ++q) acc[q] = 0.0f;
                    passN<2, 2, true>(WbX + rX, Dc,  x0, x1, x2, x3, warp, lane, acc);
                    passN<2, 4, true>(WbV + rV, DNc, v0, v1, v2, v3, warp, lane, acc);
                    reduceN<8>(acc, sh[0], warp, lane);
#pragma unroll
                    for (int q = 0; q < 8; ++q) acc[q] = 0.0f;
                    passN<2, 2, true>(WaX + rX, Dc,  x0, x1, x2, x3, warp, lane, acc);
                    passN<2, 4, true>(WaV + rV, DNc, v0, v1, v2, v3, warp, lane, acc);
                    reduceN<8>(acc, sh[1], warp, lane);
#pragma unroll
                    for (int q = 0; q < 8; ++q) acc[q] = 0.0f;
                    passN<2, 2, true>(WtX + rX, Dc,  x0, x1, x2, x3, warp, lane, acc);
                    passN<2, 4, true>(WtV + rV, DNc, v0, v1, v2, v3, warp, lane, acc);
                    reduceN<8>(acc, sh[2], warp, lane);
#pragma unroll
                    for (int q = 0; q < 8; ++q) acc[q] = 0.0f;
                    passN<2, 2, true>(Win + rX, Dc, x0, x1, x2, x3, warp, lane, acc);
                    reduceN<8>(acc, sh[3], warp, lane);
                    __syncthreads();
                    if (tid < 8) {
                        int r = tid >> 2, b = tid & 3;
                        size_t n = n0 + r;
                        float pB = sh[0][tid][0] + sh[0][tid][1] + sh[0][tid][2] + sh[0][tid][3];
                        float pA = sh[1][tid][0] + sh[1][tid][1] + sh[1][tid][2] + sh[1][tid][3];
                        float pT = sh[2][tid][0] + sh[2][tid][1] + sh[2][tid][2] + sh[2][tid][3];
                        float pI = sh[3][tid][0] + sh[3][tid][1] + sh[3][tid][2] + sh[3][tid][3];
                        float beta  = sigmf_(pB + __ldg(b_beta  + (size_t)i * DNc + n));
                        float alpha = sigmf_(pA + __ldg(b_alpha + (size_t)i * DNc + n));
                        float vth   = 0.1f + softplusf_(pT + __ldg(b_th + (size_t)i * DNc + n));
                        float vold  = Vi[(size_t)b * DNc + n];
                        float vnew  = beta * vold + alpha * pI;
                        float spv   = ((vnew - vth) >= 0.0f) ? 1.0f : 0.0f;
                        Vo[(size_t)b * DNc + n]   = vnew - spv * vth;
                        g_sp[(size_t)b * DNc + n] = spv;
                    }
                }
                grid_sync();

                // ---- blk2: 1 row/block, gate/skip/out + PLIF + output spike ----
                {
                    int xo = Kc + (i & 1);
                    size_t j = (size_t)blk;
                    const float* x = xsel_ptr(xin);
                    float* xout = g_xbuf[xo - Kc];
                    const float* x0 = x;           const float* x1 = x + Dc;
                    const float* x2 = x + 2 * Dc;  const float* x3 = x + 3 * Dc;
                    const float* s0 = g_sp;            const float* s1 = g_sp + DNc;
                    const float* s2 = g_sp + 2 * DNc;  const float* s3 = g_sp + 3 * DNc;
                    size_t rD = ((size_t)i * Dc + j) * Dc;
                    size_t rN = ((size_t)i * Dc + j) * DNc;
                    float acc[4];
#pragma unroll
                    for (int q = 0; q < 4; ++q) acc[q] = 0.0f;
                    passN<1, 2, false>(Wgate + rD, Dc, x0, x1, x2, x3, warp, lane, acc);
                    reduceN<4>(acc, sh[0], warp, lane);
#pragma unroll
                    for (int q = 0; q < 4; ++q) acc[q] = 0.0f;
                    passN<1, 2, false>(Wskip + rD, Dc, x0, x1, x2, x3, warp, lane, acc);
                    reduceN<4>(acc, sh[1], warp, lane);
#pragma unroll
                    for (int q = 0; q < 4; ++q) acc[q] = 0.0f;
                    passN<1, 4, false>(Wout + rN, DNc, s0, s1, s2, s3, warp, lane, acc);
                    reduceN<4>(acc, sh[2], warp, lane);
                    __syncthreads();
                    if (tid < 4) {
                        int b = tid;
                        float g  = sh[0][tid][0] + sh[0][tid][1] + sh[0][tid][2] + sh[0][tid][3];
                        float sk = sh[1][tid][0] + sh[1][tid][1] + sh[1][tid][2] + sh[1][tid][3];
                        float o  = sh[2][tid][0] + sh[2][tid][1] + sh[2][tid][2] + sh[2][tid][3];
                        float cur = sigmf_(g) * o + sk;
                        float tau = sigmf_(__ldg(plif_w + i));
                        float vt  = __ldg(out_vth + i);
                        size_t ui = ((size_t)i * Bc + b) * Dc + j;
                        float uu = g_u[ui];
                        uu = uu + (cur - uu) * tau;
                        float so = ((uu - vt) >= 0.0f) ? 1.0f : 0.0f;
                        g_u[ui] = (1.0f - so) * uu;
                        xout[(size_t)b * Dc + j] = so;
                        if (i == NBc - 1) {
                            float wk = 1.0f / (float)(1 << (k + 1));
                            g_decoded[(size_t)b * Dc + j] += wk * so;
                        }
                    }
                    xin = xo;
                }
                grid_sync();
            }
            par ^= 1;                            // V ping-pong flips once per frame
        }

        // ================= decoder: 1 row/block =================
        {
            size_t j = (size_t)blk;
            const float* d0 = g_decoded;           const float* d1 = g_decoded + Dc;
            const float* d2 = g_decoded + 2 * Dc;  const float* d3 = g_decoded + 3 * Dc;
            float acc[4];
#pragma unroll
            for (int q = 0; q < 4; ++q) acc[q] = 0.0f;
            passN<1, 2, false>(decW + j * Dc, Dc, d0, d1, d2, d3, warp, lane, acc);
            reduceN<4>(acc, sh[0], warp, lane);
            __syncthreads();
            if (tid < 4) {
                int b = tid;
                float s = sh[0][tid][0] + sh[0][tid][1] + sh[0][tid][2] + sh[0][tid][3];
                g_hh[(size_t)b * Dc + j] = s + __ldg(decb + j);
            }
        }
        grid_sync();

        // ================= RMSNorm (block 0 only) =================
        if (blk == 0) {
            __shared__ float srstd[Bc];
            if (warp < Bc) {
                float s = 0.0f;
                for (int j = lane; j < Dc; j += 32) {
                    float v = g_hh[warp * Dc + j];
                    s = fmaf(v, v, s);
                }
                s = warp_sum(s);
                if (lane == 0) srstd[warp] = 1.0f / sqrtf(s / (float)Dc + 1e-6f);
            }
            __syncthreads();
            for (int idx = tid; idx < Bc * Dc; idx += NTHR) {
                g_hh[idx] = g_hh[idx] * norm_w[idx & (Dc - 1)] * srstd[idx >> 10];
            }
        }
        grid_sync();

        // ================= LM head: 75 x (1024 blocks x 2 rows) =================
        {
            const float* h0 = g_hh;           const float* h1 = g_hh + Dc;
            const float* h2 = g_hh + 2 * Dc;  const float* h3 = g_hh + 3 * Dc;
            for (int it = 0; it < (VOCABc + NBLK * 2 - 1) / (NBLK * 2); ++it) {
                size_t v0 = (size_t)it * (NBLK * 2) + (size_t)blk * 2;
                if (v0 < VOCABc) {
                    float acc[8];
#pragma unroll
                    for (int q = 0; q < 8; ++q) acc[q] = 0.0f;
                    passN<2, 2, true>(embed + v0 * Dc, Dc, h0, h1, h2, h3, warp, lane, acc);
                    reduceN<8>(acc, sh[0], warp, lane);
                    __syncthreads();
                    if (tid < 8) {
                        int r = tid >> 2, b = tid & 3;
                        float s = sh[0][tid][0] + sh[0][tid][1] + sh[0][tid][2] + sh[0][tid][3];
                        out[((size_t)b * Sc + t) * VOCABc + v0 + r] = s;
                    }
                    __syncthreads();   // protect sh reuse across iterations
                }
            }
        }
        // no grid_sync needed here: the sync after enc(t+1) orders lmhead(t)
        // against the first writer of g_hh (dec at t+1).
    }
}

// ---------------- host driver: ONE graph node ----------------
extern "C" void kernel_launch(void* const* d_in, const int* in_sizes, int n_in,
                              void* d_out, int out_size)
{
    (void)in_sizes; (void)n_in; (void)out_size;
    snn_mono_kernel<<<NBLK, NTHR>>>(
        (const int*)d_in[0],  (const float*)d_in[1],  (const float*)d_in[2],
        (const float*)d_in[3], (const float*)d_in[4], (const float*)d_in[5],
        (const float*)d_in[6], (const float*)d_in[7], (const float*)d_in[8],
        (const float*)d_in[9], (const float*)d_in[10], (const float*)d_in[11],
        (const float*)d_in[12], (const float*)d_in[13], (const float*)d_in[14],
        (const float*)d_in[15], (const float*)d_in[16], (const float*)d_in[17],
        (const float*)d_in[18], (const float*)d_in[19], (const float*)d_in[20],
        (const float*)d_in[21], (float*)d_out);
}

// round 13
// speedup vs baseline: 1.7717x; 1.7717x over previous
#include <cuda_runtime.h>
#include <stdint.h>
#include <math.h>

#define Bc     4
#define Sc     16
#define Dc     1024
#define DNc    2048
#define Kc     8
#define NBc    4
#define VOCABc 151936
#define NBLK   512
#define NTHR   128
#define STAGES 3
#define PFD    2

// ---------------- device state (static; no allocation) ----------------
__device__ float g_Vst[2 * NBc * Bc * DNc];   // ping-pong V state [par][blk][b][n]
__device__ float g_u[NBc * Bc * Dc];          // PLIF output-neuron state
__device__ float g_xbuf[2][Bc * Dc];          // ping-pong spike vectors between blocks
__device__ float g_sp[Bc * DNc];              // internal spikes of current block
__device__ float g_frames[Kc * Bc * Dc];      // binary frames for current token
__device__ float g_decoded[Bc * Dc];          // weighted sum of output frames
__device__ float g_hh[Bc * Dc];               // decoded @ dec_W.T (+rmsnorm in place)

// software grid barrier state (self-resetting: count returns to 0, gen monotonic)
__device__ unsigned g_bar_count;
__device__ volatile unsigned g_bar_gen;

// ---------------- helpers ----------------
__device__ __forceinline__ float sigmf_(float a) { return 1.0f / (1.0f + expf(-a)); }
__device__ __forceinline__ float softplusf_(float a) {
    return fmaxf(a, 0.0f) + log1pf(expf(-fabsf(a)));
}
__device__ __forceinline__ float warp_sum(float v) {
    v += __shfl_xor_sync(0xffffffffu, v, 16);
    v += __shfl_xor_sync(0xffffffffu, v, 8);
    v += __shfl_xor_sync(0xffffffffu, v, 4);
    v += __shfl_xor_sync(0xffffffffu, v, 2);
    v += __shfl_xor_sync(0xffffffffu, v, 1);
    return v;
}
__device__ __forceinline__ float dot4(float acc, float4 wv, float4 av) {
    return fmaf(wv.x, av.x, fmaf(wv.y, av.y, fmaf(wv.z, av.z, fmaf(wv.w, av.w, acc))));
}

// Two-variable grid barrier. All 512 blocks are co-resident (launch_bounds(128,4)
// -> >=4 blocks/SM, smem 24.25KB -> 4 fit -> capacity 592 >= 512).
__device__ __forceinline__ void grid_sync() {
    __syncthreads();
    if (threadIdx.x == 0) {
        __threadfence();                       // release prior writes
        unsigned gen = g_bar_gen;
        if (atomicAdd(&g_bar_count, 1u) == (unsigned)(gridDim.x - 1)) {
            g_bar_count = 0;
            __threadfence();
            g_bar_gen = gen + 1;               // release
        } else {
            while (g_bar_gen == gen) __nanosleep(64);
        }
        __threadfence();                       // acquire
    }
    __syncthreads();
}

// ---------------- cp.async machinery ----------------
__device__ __forceinline__ void cp16(uint32_t dst, const void* src, uint64_t pol) {
    asm volatile("cp.async.cg.shared.global.L2::cache_hint [%0], [%1], 16, %2;"
                 :: "r"(dst), "l"(src), "l"(pol) : "memory");
}
__device__ __forceinline__ void cp_commit() {
    asm volatile("cp.async.commit_group;" ::: "memory");
}
template <int N>
__device__ __forceinline__ void cp_wait() {
    asm volatile("cp.async.wait_group %0;" :: "n"(N) : "memory");
}
__device__ __forceinline__ uint64_t make_evict_first_policy() {
    uint64_t pol;
    asm("createpolicy.fractional.L2::evict_first.b64 %0;" : "=l"(pol));
    return pol;
}

// ---------------- GEMV inner passes ----------------
// passN: plain version (R10-identical). NR rows x 4 batches, 4-warp column split.
// Weights streamed with __ldcs, operands via __ldg. FMA order fixed.
template <int NR, int NF4>
__device__ __forceinline__ void passN(
    const float* __restrict__ wrow0, int ldw,
    const float* __restrict__ px0, const float* __restrict__ px1,
    const float* __restrict__ px2, const float* __restrict__ px3,
    int warp, int lane, float* acc)
{
    const float4* a0 = (const float4*)px0;
    const float4* a1 = (const float4*)px1;
    const float4* a2 = (const float4*)px2;
    const float4* a3 = (const float4*)px3;
    int cbase = warp * NF4 * 32 + lane;
#pragma unroll
    for (int it = 0; it < NF4; ++it) {
        int idx = cbase + it * 32;
        float4 b0 = __ldg(a0 + idx);
        float4 b1 = __ldg(a1 + idx);
        float4 b2 = __ldg(a2 + idx);
        float4 b3 = __ldg(a3 + idx);
#pragma unroll
        for (int r = 0; r < NR; ++r) {
            const float4* wr = (const float4*)(wrow0 + (size_t)r * ldw);
            float4 q = __ldcs(wr + idx);
            acc[r * 4 + 0] = dot4(acc[r * 4 + 0], q, b0);
            acc[r * 4 + 1] = dot4(acc[r * 4 + 1], q, b1);
            acc[r * 4 + 2] = dot4(acc[r * 4 + 2], q, b2);
            acc[r * 4 + 3] = dot4(acc[r * 4 + 3], q, b3);
        }
    }
}

// pass4_cp: NR=4 version with weights staged through SMEM via cp.async
// (triple buffer, PFD=2 stages prefetched). Per-lane self-copy: lane L copies
// exactly the 16B it will read, so cp.async.wait_group alone orders it.
// Consumed values and FMA order are IDENTICAL to passN<4,NF4> -> bit-exact.
template <int NF4>
__device__ __forceinline__ void pass4_cp(
    const float* __restrict__ wrow0, int ldw,
    const float* __restrict__ px0, const float* __restrict__ px1,
    const float* __restrict__ px2, const float* __restrict__ px3,
    int warp, int lane, float* acc, float4* wbuf /* [STAGES][4][32] this warp */,
    uint64_t pol)
{
    const float4* a0 = (const float4*)px0;
    const float4* a1 = (const float4*)px1;
    const float4* a2 = (const float4*)px2;
    const float4* a3 = (const float4*)px3;
    int cbase = warp * NF4 * 32 + lane;
    uint32_t sb = (uint32_t)__cvta_generic_to_shared(wbuf);

    // prologue: PFD commit groups (real issues only for stage < NF4)
#pragma unroll
    for (int p = 0; p < PFD; ++p) {
        if (p < NF4) {
            int idx = cbase + p * 32;
#pragma unroll
            for (int r = 0; r < 4; ++r) {
                const float4* g = (const float4*)(wrow0 + (size_t)r * ldw) + idx;
                cp16(sb + (uint32_t)((((p % STAGES) * 4 + r) * 32 + lane) * 16), g, pol);
            }
        }
        cp_commit();
    }
#pragma unroll
    for (int it = 0; it < NF4; ++it) {
        int pfs = it + PFD;
        if (pfs < NF4) {
            int idx = cbase + pfs * 32;
#pragma unroll
            for (int r = 0; r < 4; ++r) {
                const float4* g = (const float4*)(wrow0 + (size_t)r * ldw) + idx;
                cp16(sb + (uint32_t)((((pfs % STAGES) * 4 + r) * 32 + lane) * 16), g, pol);
            }
        }
        cp_commit();   // one group per iteration (possibly empty) -> constant wait depth
        int idx = cbase + it * 32;
        float4 b0 = __ldg(a0 + idx);
        float4 b1 = __ldg(a1 + idx);
        float4 b2 = __ldg(a2 + idx);
        float4 b3 = __ldg(a3 + idx);
        cp_wait<PFD>();   // stage `it` complete
        int s = (it % STAGES) * 4;
        float4 q0 = wbuf[(s + 0) * 32 + lane];
        float4 q1 = wbuf[(s + 1) * 32 + lane];
        float4 q2 = wbuf[(s + 2) * 32 + lane];
        float4 q3 = wbuf[(s + 3) * 32 + lane];
        acc[0]  = dot4(acc[0],  q0, b0); acc[1]  = dot4(acc[1],  q0, b1);
        acc[2]  = dot4(acc[2],  q0, b2); acc[3]  = dot4(acc[3],  q0, b3);
        acc[4]  = dot4(acc[4],  q1, b0); acc[5]  = dot4(acc[5],  q1, b1);
        acc[6]  = dot4(acc[6],  q1, b2); acc[7]  = dot4(acc[7],  q1, b3);
        acc[8]  = dot4(acc[8],  q2, b0); acc[9]  = dot4(acc[9],  q2, b1);
        acc[10] = dot4(acc[10], q2, b2); acc[11] = dot4(acc[11], q2, b3);
        acc[12] = dot4(acc[12], q3, b0); acc[13] = dot4(acc[13], q3, b1);
        acc[14] = dot4(acc[14], q3, b2); acc[15] = dot4(acc[15], q3, b3);
    }
}

template <int NA>
__device__ __forceinline__ void reduceN(const float* acc, float (*sh)[4], int warp, int lane) {
#pragma unroll
    for (int i = 0; i < NA; ++i) {
        float v = warp_sum(acc[i]);
        if (lane == 0) sh[i][warp] = v;
    }
}

__device__ __forceinline__ const float* xsel_ptr(int sel) {
    return (sel < Kc) ? (g_frames + (size_t)sel * Bc * Dc) : g_xbuf[sel - Kc];
}

// ---------------- the whole model as ONE persistent kernel ----------------
__global__ void __launch_bounds__(NTHR, 4) snn_mono_kernel(
    const int* __restrict__ tok, const float* __restrict__ embed,
    const float* __restrict__ norm_w,
    const float* __restrict__ encW, const float* __restrict__ encb,
    const float* __restrict__ decW, const float* __restrict__ decb,
    const float* __restrict__ Win, const float* __restrict__ WbX,
    const float* __restrict__ WaX, const float* __restrict__ WtX,
    const float* __restrict__ WbV, const float* __restrict__ WaV,
    const float* __restrict__ WtV,
    const float* __restrict__ b_beta, const float* __restrict__ b_alpha,
    const float* __restrict__ b_th,
    const float* __restrict__ Wgate, const float* __restrict__ Wskip,
    const float* __restrict__ Wout,
    const float* __restrict__ plif_w, const float* __restrict__ out_vth,
    float* __restrict__ out)
{
    const int blk  = blockIdx.x;           // 0..511
    const int tid  = threadIdx.x;
    const int warp = tid >> 5, lane = tid & 31;
    __shared__ float sh[4][16][4];
    __shared__ float4 cpbuf[4][STAGES * 4 * 32];   // 24KB: per-warp weight stages
    float4* wbuf = cpbuf[warp];
    const uint64_t pol = make_evict_first_policy();

    // ---- init state (deterministic every replay) ----
    for (int i = blk * NTHR + tid; i < NBc * Bc * DNc; i += NBLK * NTHR) g_Vst[i] = 0.0f;
    for (int i = blk * NTHR + tid; i < NBc * Bc * Dc;  i += NBLK * NTHR) g_u[i]   = 0.0f;
    grid_sync();

    int par = 0;
    for (int t = 0; t < Sc; ++t) {
        // ================= encoder: 2 rows/block =================
        {
            int j0 = blk * 2;
            const float* e0 = embed + (size_t)__ldg(tok + 0 * Sc + t) * Dc;
            const float* e1 = embed + (size_t)__ldg(tok + 1 * Sc + t) * Dc;
            const float* e2 = embed + (size_t)__ldg(tok + 2 * Sc + t) * Dc;
            const float* e3 = embed + (size_t)__ldg(tok + 3 * Sc + t) * Dc;
            float acc[8];
#pragma unroll
            for (int i = 0; i < 8; ++i) acc[i] = 0.0f;
            passN<2, 2>(encW + (size_t)j0 * Dc, Dc, e0, e1, e2, e3, warp, lane, acc);
            reduceN<8>(acc, sh[0], warp, lane);
            __syncthreads();
            if (tid < 8) {
                int r = tid >> 2, b = tid & 3;
                int j = j0 + r;
                float s = sh[0][tid][0] + sh[0][tid][1] + sh[0][tid][2] + sh[0][tid][3];
                float res = sigmf_(s + encb[j]);
#pragma unroll
                for (int k = 0; k < Kc; ++k) {
                    float bit = (res >= 0.5f) ? 1.0f : 0.0f;
                    g_frames[((size_t)k * Bc + b) * Dc + j] = bit;
                    res = (res - 0.5f * bit) * 2.0f;
                }
                g_decoded[b * Dc + j] = 0.0f;
            }
        }
        grid_sync();

        // ================= K frames x NB blocks =================
        for (int k = 0; k < Kc; ++k) {
            int xin = k;                         // frame k feeds block 0
            for (int i = 0; i < NBc; ++i) {
                // ---- blk1: 4 rows/block, fused 7-GEMV + V update + spike ----
                {
                    size_t n0 = (size_t)blk * 4;
                    const float* x  = xsel_ptr(xin);
                    const float* Vi = g_Vst + ((size_t)par * NBc + i) * Bc * DNc;
                    float*       Vo = g_Vst + ((size_t)(par ^ 1) * NBc + i) * Bc * DNc;
                    const float* x0 = x;            const float* x1 = x + Dc;
                    const float* x2 = x + 2 * Dc;   const float* x3 = x + 3 * Dc;
                    const float* v0 = Vi;           const float* v1 = Vi + DNc;
                    const float* v2 = Vi + 2 * DNc; const float* v3 = Vi + 3 * DNc;
                    size_t rX = ((size_t)i * DNc + n0) * Dc;
                    size_t rV = ((size_t)i * DNc + n0) * DNc;
                    float acc[16];
#pragma unroll
                    for (int q = 0; q < 16; ++q) acc[q] = 0.0f;
                    pass4_cp<2>(WbX + rX, Dc,  x0, x1, x2, x3, warp, lane, acc, wbuf, pol);
                    pass4_cp<4>(WbV + rV, DNc, v0, v1, v2, v3, warp, lane, acc, wbuf, pol);
                    reduceN<16>(acc, sh[0], warp, lane);
#pragma unroll
                    for (int q = 0; q < 16; ++q) acc[q] = 0.0f;
                    pass4_cp<2>(WaX + rX, Dc,  x0, x1, x2, x3, warp, lane, acc, wbuf, pol);
                    pass4_cp<4>(WaV + rV, DNc, v0, v1, v2, v3, warp, lane, acc, wbuf, pol);
                    reduceN<16>(acc, sh[1], warp, lane);
#pragma unroll
                    for (int q = 0; q < 16; ++q) acc[q] = 0.0f;
                    pass4_cp<2>(WtX + rX, Dc,  x0, x1, x2, x3, warp, lane, acc, wbuf, pol);
                    pass4_cp<4>(WtV + rV, DNc, v0, v1, v2, v3, warp, lane, acc, wbuf, pol);
                    reduceN<16>(acc, sh[2], warp, lane);
#pragma unroll
                    for (int q = 0; q < 16; ++q) acc[q] = 0.0f;
                    pass4_cp<2>(Win + rX, Dc, x0, x1, x2, x3, warp, lane, acc, wbuf, pol);
                    reduceN<16>(acc, sh[3], warp, lane);
                    __syncthreads();
                    if (tid < 16) {
                        int r = tid >> 2, b = tid & 3;
                        size_t n = n0 + r;
                        float pB = sh[0][tid][0] + sh[0][tid][1] + sh[0][tid][2] + sh[0][tid][3];
                        float pA = sh[1][tid][0] + sh[1][tid][1] + sh[1][tid][2] + sh[1][tid][3];
                        float pT = sh[2][tid][0] + sh[2][tid][1] + sh[2][tid][2] + sh[2][tid][3];
                        float pI = sh[3][tid][0] + sh[3][tid][1] + sh[3][tid][2] + sh[3][tid][3];
                        float beta  = sigmf_(pB + b_beta[(size_t)i * DNc + n]);
                        float alpha = sigmf_(pA + b_alpha[(size_t)i * DNc + n]);
                        float vth   = 0.1f + softplusf_(pT + b_th[(size_t)i * DNc + n]);
                        float vold  = Vi[(size_t)b * DNc + n];
                        float vnew  = beta * vold + alpha * pI;
                        float spv   = ((vnew - vth) >= 0.0f) ? 1.0f : 0.0f;
                        Vo[(size_t)b * DNc + n]   = vnew - spv * vth;
                        g_sp[(size_t)b * DNc + n] = spv;
                    }
                }
                grid_sync();

                // ---- blk2: 2 rows/block, gate/skip/out + PLIF + output spike ----
                {
                    int xo = Kc + (i & 1);
                    size_t j0 = (size_t)blk * 2;
                    const float* x = xsel_ptr(xin);
                    float* xout = g_xbuf[xo - Kc];
                    const float* x0 = x;           const float* x1 = x + Dc;
                    const float* x2 = x + 2 * Dc;  const float* x3 = x + 3 * Dc;
                    const float* s0 = g_sp;            const float* s1 = g_sp + DNc;
                    const float* s2 = g_sp + 2 * DNc;  const float* s3 = g_sp + 3 * DNc;
                    size_t rD = ((size_t)i * Dc + j0) * Dc;
                    size_t rN = ((size_t)i * Dc + j0) * DNc;
                    float acc[8];
#pragma unroll
                    for (int q = 0; q < 8; ++q) acc[q] = 0.0f;
                    passN<2, 2>(Wgate + rD, Dc, x0, x1, x2, x3, warp, lane, acc);
                    reduceN<8>(acc, sh[0], warp, lane);
#pragma unroll
                    for (int q = 0; q < 8; ++q) acc[q] = 0.0f;
                    passN<2, 2>(Wskip + rD, Dc, x0, x1, x2, x3, warp, lane, acc);
                    reduceN<8>(acc, sh[1], warp, lane);
#pragma unroll
                    for (int q = 0; q < 8; ++q) acc[q] = 0.0f;
                    passN<2, 4>(Wout + rN, DNc, s0, s1, s2, s3, warp, lane, acc);
                    reduceN<8>(acc, sh[2], warp, lane);
                    __syncthreads();
                    if (tid < 8) {
                        int r = tid >> 2, b = tid & 3;
                        size_t j = j0 + r;
                        float g  = sh[0][tid][0] + sh[0][tid][1] + sh[0][tid][2] + sh[0][tid][3];
                        float sk = sh[1][tid][0] + sh[1][tid][1] + sh[1][tid][2] + sh[1][tid][3];
                        float o  = sh[2][tid][0] + sh[2][tid][1] + sh[2][tid][2] + sh[2][tid][3];
                        float cur = sigmf_(g) * o + sk;
                        float tau = sigmf_(plif_w[i]);
                        float vt  = out_vth[i];
                        size_t ui = ((size_t)i * Bc + b) * Dc + j;
                        float uu = g_u[ui];
                        uu = uu + (cur - uu) * tau;
                        float so = ((uu - vt) >= 0.0f) ? 1.0f : 0.0f;
                        g_u[ui] = (1.0f - so) * uu;
                        xout[(size_t)b * Dc + j] = so;
                        if (i == NBc - 1) {
                            float wk = 1.0f / (float)(1 << (k + 1));
                            g_decoded[(size_t)b * Dc + j] += wk * so;
                        }
                    }
                    xin = xo;
                }
                grid_sync();
            }
            par ^= 1;                            // V ping-pong flips once per frame
        }

        // ================= decoder: 2 rows/block =================
        {
            size_t j0 = (size_t)blk * 2;
            const float* d0 = g_decoded;           const float* d1 = g_decoded + Dc;
            const float* d2 = g_decoded + 2 * Dc;  const float* d3 = g_decoded + 3 * Dc;
            float acc[8];
#pragma unroll
            for (int q = 0; q < 8; ++q) acc[q] = 0.0f;
            passN<2, 2>(decW + j0 * Dc, Dc, d0, d1, d2, d3, warp, lane, acc);
            reduceN<8>(acc, sh[0], warp, lane);
            __syncthreads();
            if (tid < 8) {
                int r = tid >> 2, b = tid & 3;
                size_t j = j0 + r;
                float s = sh[0][tid][0] + sh[0][tid][1] + sh[0][tid][2] + sh[0][tid][3];
                g_hh[(size_t)b * Dc + j] = s + decb[j];
            }
        }
        grid_sync();

        // ================= RMSNorm (block 0 only) =================
        if (blk == 0) {
            __shared__ float srstd[Bc];
            if (warp < Bc) {
                float s = 0.0f;
                for (int j = lane; j < Dc; j += 32) {
                    float v = g_hh[warp * Dc + j];
                    s = fmaf(v, v, s);
                }
                s = warp_sum(s);
                if (lane == 0) srstd[warp] = 1.0f / sqrtf(s / (float)Dc + 1e-6f);
            }
            __syncthreads();
            for (int idx = tid; idx < Bc * Dc; idx += NTHR) {
                g_hh[idx] = g_hh[idx] * norm_w[idx & (Dc - 1)] * srstd[idx >> 10];
            }
        }
        grid_sync();

        // ================= LM head: 75 x (512 blocks x 4 rows) =================
        {
            const float* h0 = g_hh;           const float* h1 = g_hh + Dc;
            const float* h2 = g_hh + 2 * Dc;  const float* h3 = g_hh + 3 * Dc;
            for (int it = 0; it < (VOCABc + NBLK * 4 - 1) / (NBLK * 4); ++it) {
                size_t v0 = (size_t)it * (NBLK * 4) + (size_t)blk * 4;
                if (v0 < VOCABc) {
                    float acc[16];
#pragma unroll
                    for (int q = 0; q < 16; ++q) acc[q] = 0.0f;
                    pass4_cp<2>(embed + v0 * Dc, Dc, h0, h1, h2, h3, warp, lane, acc, wbuf, pol);
                    reduceN<16>(acc, sh[0], warp, lane);
                    __syncthreads();
                    if (tid < 16) {
                        int r = tid >> 2, b = tid & 3;
                        float s = sh[0][tid][0] + sh[0][tid][1] + sh[0][tid][2] + sh[0][tid][3];
                        out[((size_t)b * Sc + t) * VOCABc + v0 + r] = s;
                    }
                    __syncthreads();   // protect sh reuse across iterations
                }
            }
        }
        // no grid_sync needed here: the sync after enc(t+1) orders lmhead(t)
        // against the first writer of g_hh (dec at t+1).
    }
}

// ---------------- host driver: ONE graph node ----------------
extern "C" void kernel_launch(void* const* d_in, const int* in_sizes, int n_in,
                              void* d_out, int out_size)
{
    (void)in_sizes; (void)n_in; (void)out_size;
    snn_mono_kernel<<<NBLK, NTHR>>>(
        (const int*)d_in[0],  (const float*)d_in[1],  (const float*)d_in[2],
        (const float*)d_in[3], (const float*)d_in[4], (const float*)d_in[5],
        (const float*)d_in[6], (const float*)d_in[7], (const float*)d_in[8],
        (const float*)d_in[9], (const float*)d_in[10], (const float*)d_in[11],
        (const float*)d_in[12], (const float*)d_in[13], (const float*)d_in[14],
        (const float*)d_in[15], (const float*)d_in[16], (const float*)d_in[17],
        (const float*)d_in[18], (const float*)d_in[19], (const float*)d_in[20],
        (const float*)d_in[21], (float*)d_out);
}

// round 14
// speedup vs baseline: 1.8472x; 1.0426x over previous
#include <cuda_runtime.h>
#include <stdint.h>
#include <math.h>

#define Bc     4
#define Sc     16
#define Dc     1024
#define DNc    2048
#define Kc     8
#define NBc    4
#define VOCABc 151936
#define NBLK   512
#define NTHR   128
#define STAGES 5
#define PFD    3

// ---------------- device state (static; no allocation) ----------------
__device__ float g_Vst[2 * NBc * Bc * DNc];
__device__ float g_u[NBc * Bc * Dc];
__device__ float g_xbuf[2][Bc * Dc];
__device__ float g_sp[Bc * DNc];
__device__ float g_frames[Kc * Bc * Dc];
__device__ float g_decoded[Bc * Dc];
__device__ float g_hh[Bc * Dc];

__device__ unsigned g_bar_count;
__device__ volatile unsigned g_bar_gen;

// ---------------- helpers ----------------
__device__ __forceinline__ float sigmf_(float a) { return 1.0f / (1.0f + expf(-a)); }
__device__ __forceinline__ float softplusf_(float a) {
    return fmaxf(a, 0.0f) + log1pf(expf(-fabsf(a)));
}
__device__ __forceinline__ float warp_sum(float v) {
    v += __shfl_xor_sync(0xffffffffu, v, 16);
    v += __shfl_xor_sync(0xffffffffu, v, 8);
    v += __shfl_xor_sync(0xffffffffu, v, 4);
    v += __shfl_xor_sync(0xffffffffu, v, 2);
    v += __shfl_xor_sync(0xffffffffu, v, 1);
    return v;
}
__device__ __forceinline__ float dot4(float acc, float4 wv, float4 av) {
    return fmaf(wv.x, av.x, fmaf(wv.y, av.y, fmaf(wv.z, av.z, fmaf(wv.w, av.w, acc))));
}

// Grid barrier; all 512 blocks co-resident (launch_bounds(128,4), smem 41.3KB -> 4/SM).
__device__ __forceinline__ void grid_sync() {
    __syncthreads();
    if (threadIdx.x == 0) {
        __threadfence();
        unsigned gen = g_bar_gen;
        if (atomicAdd(&g_bar_count, 1u) == (unsigned)(gridDim.x - 1)) {
            g_bar_count = 0;
            __threadfence();
            g_bar_gen = gen + 1;
        } else {
            while (g_bar_gen == gen) __nanosleep(64);
        }
        __threadfence();
    }
    __syncthreads();
}

// ---------------- cp.async machinery ----------------
__device__ __forceinline__ void cp16(uint32_t dst, const void* src, uint64_t pol) {
    asm volatile("cp.async.cg.shared.global.L2::cache_hint [%0], [%1], 16, %2;"
                 :: "r"(dst), "l"(src), "l"(pol) : "memory");
}
__device__ __forceinline__ void cp_commit() {
    asm volatile("cp.async.commit_group;" ::: "memory");
}
template <int N>
__device__ __forceinline__ void cp_wait() {
    asm volatile("cp.async.wait_group %0;" :: "n"(N) : "memory");
}
__device__ __forceinline__ uint64_t pol_evict_first() {
    uint64_t p; asm("createpolicy.fractional.L2::evict_first.b64 %0;" : "=l"(p)); return p;
}
__device__ __forceinline__ uint64_t pol_evict_last() {
    uint64_t p; asm("createpolicy.fractional.L2::evict_last.b64 %0;" : "=l"(p)); return p;
}

// ---- chained-pipeline macros (4-row and 2-row tiles) ----
// stage layout per warp: wbuf[(slot*4 + row)*32 + lane]
#define ISS4(SLOT, WP, LD, IDX, POL) do {                                          \
    const float* _wp = (WP); const size_t _ldw = (LD); const int _ix = (IDX);      \
    cp16(sb + (uint32_t)(((SLOT)*4+0)*32+lane)*16u, (const float4*)(_wp) + _ix, POL);            \
    cp16(sb + (uint32_t)(((SLOT)*4+1)*32+lane)*16u, (const float4*)(_wp+_ldw) + _ix, POL);       \
    cp16(sb + (uint32_t)(((SLOT)*4+2)*32+lane)*16u, (const float4*)(_wp+2*_ldw) + _ix, POL);     \
    cp16(sb + (uint32_t)(((SLOT)*4+3)*32+lane)*16u, (const float4*)(_wp+3*_ldw) + _ix, POL);     \
    cp_commit();                                                                   \
} while (0)

#define ISS2(SLOT, WP, LD, IDX, POL) do {                                          \
    const float* _wp = (WP); const size_t _ldw = (LD); const int _ix = (IDX);      \
    cp16(sb + (uint32_t)(((SLOT)*4+0)*32+lane)*16u, (const float4*)(_wp) + _ix, POL);            \
    cp16(sb + (uint32_t)(((SLOT)*4+1)*32+lane)*16u, (const float4*)(_wp+_ldw) + _ix, POL);       \
    cp_commit();                                                                   \
} while (0)

#define ISS_NONE() cp_commit()

#define CONS4(SLOT, IDX, P0, P1, P2, P3) do {                                      \
    const int _ix = (IDX);                                                         \
    float4 _b0 = __ldg((const float4*)(P0) + _ix);                                 \
    float4 _b1 = __ldg((const float4*)(P1) + _ix);                                 \
    float4 _b2 = __ldg((const float4*)(P2) + _ix);                                 \
    float4 _b3 = __ldg((const float4*)(P3) + _ix);                                 \
    cp_wait<PFD>();                                                                \
    float4 _q0 = wbuf[((SLOT)*4+0)*32+lane];                                       \
    float4 _q1 = wbuf[((SLOT)*4+1)*32+lane];                                       \
    float4 _q2 = wbuf[((SLOT)*4+2)*32+lane];                                       \
    float4 _q3 = wbuf[((SLOT)*4+3)*32+lane];                                       \
    acc[0]  = dot4(acc[0],  _q0, _b0); acc[1]  = dot4(acc[1],  _q0, _b1);          \
    acc[2]  = dot4(acc[2],  _q0, _b2); acc[3]  = dot4(acc[3],  _q0, _b3);          \
    acc[4]  = dot4(acc[4],  _q1, _b0); acc[5]  = dot4(acc[5],  _q1, _b1);          \
    acc[6]  = dot4(acc[6],  _q1, _b2); acc[7]  = dot4(acc[7],  _q1, _b3);          \
    acc[8]  = dot4(acc[8],  _q2, _b0); acc[9]  = dot4(acc[9],  _q2, _b1);          \
    acc[10] = dot4(acc[10], _q2, _b2); acc[11] = dot4(acc[11], _q2, _b3);          \
    acc[12] = dot4(acc[12], _q3, _b0); acc[13] = dot4(acc[13], _q3, _b1);          \
    acc[14] = dot4(acc[14], _q3, _b2); acc[15] = dot4(acc[15], _q3, _b3);          \
} while (0)

#define CONS2(SLOT, IDX, P0, P1, P2, P3) do {                                      \
    const int _ix = (IDX);                                                         \
    float4 _b0 = __ldg((const float4*)(P0) + _ix);                                 \
    float4 _b1 = __ldg((const float4*)(P1) + _ix);                                 \
    float4 _b2 = __ldg((const float4*)(P2) + _ix);                                 \
    float4 _b3 = __ldg((const float4*)(P3) + _ix);                                 \
    cp_wait<PFD>();                                                                \
    float4 _q0 = wbuf[((SLOT)*4+0)*32+lane];                                       \
    float4 _q1 = wbuf[((SLOT)*4+1)*32+lane];                                       \
    acc[0] = dot4(acc[0], _q0, _b0); acc[1] = dot4(acc[1], _q0, _b1);              \
    acc[2] = dot4(acc[2], _q0, _b2); acc[3] = dot4(acc[3], _q0, _b3);              \
    acc[4] = dot4(acc[4], _q1, _b0); acc[5] = dot4(acc[5], _q1, _b1);              \
    acc[6] = dot4(acc[6], _q1, _b2); acc[7] = dot4(acc[7], _q1, _b3);              \
} while (0)

#define ZERO(N) do { _Pragma("unroll") for (int _q = 0; _q < (N); ++_q) acc[_q] = 0.0f; } while (0)

// plain pass for tiny enc/dec GEMVs (R10-identical)
template <int NR, int NF4>
__device__ __forceinline__ void passN(
    const float* __restrict__ wrow0, int ldw,
    const float* __restrict__ px0, const float* __restrict__ px1,
    const float* __restrict__ px2, const float* __restrict__ px3,
    int warp, int lane, float* acc)
{
    const float4* a0 = (const float4*)px0;
    const float4* a1 = (const float4*)px1;
    const float4* a2 = (const float4*)px2;
    const float4* a3 = (const float4*)px3;
    int cbase = warp * NF4 * 32 + lane;
#pragma unroll
    for (int it = 0; it < NF4; ++it) {
        int idx = cbase + it * 32;
        float4 b0 = __ldg(a0 + idx);
        float4 b1 = __ldg(a1 + idx);
        float4 b2 = __ldg(a2 + idx);
        float4 b3 = __ldg(a3 + idx);
#pragma unroll
        for (int r = 0; r < NR; ++r) {
            const float4* wr = (const float4*)(wrow0 + (size_t)r * ldw);
            float4 q = __ldcs(wr + idx);
            acc[r * 4 + 0] = dot4(acc[r * 4 + 0], q, b0);
            acc[r * 4 + 1] = dot4(acc[r * 4 + 1], q, b1);
            acc[r * 4 + 2] = dot4(acc[r * 4 + 2], q, b2);
            acc[r * 4 + 3] = dot4(acc[r * 4 + 3], q, b3);
        }
    }
}

template <int NA>
__device__ __forceinline__ void reduceN(const float* acc, float (*sh)[4], int warp, int lane) {
#pragma unroll
    for (int i = 0; i < NA; ++i) {
        float v = warp_sum(acc[i]);
        if (lane == 0) sh[i][warp] = v;
    }
}

__device__ __forceinline__ const float* xsel_ptr(int sel) {
    return (sel < Kc) ? (g_frames + (size_t)sel * Bc * Dc) : g_xbuf[sel - Kc];
}

// ---------------- the whole model as ONE persistent kernel ----------------
__global__ void __launch_bounds__(NTHR, 4) snn_mono_kernel(
    const int* __restrict__ tok, const float* __restrict__ embed,
    const float* __restrict__ norm_w,
    const float* __restrict__ encW, const float* __restrict__ encb,
    const float* __restrict__ decW, const float* __restrict__ decb,
    const float* __restrict__ Win, const float* __restrict__ WbX,
    const float* __restrict__ WaX, const float* __restrict__ WtX,
    const float* __restrict__ WbV, const float* __restrict__ WaV,
    const float* __restrict__ WtV,
    const float* __restrict__ b_beta, const float* __restrict__ b_alpha,
    const float* __restrict__ b_th,
    const float* __restrict__ Wgate, const float* __restrict__ Wskip,
    const float* __restrict__ Wout,
    const float* __restrict__ plif_w, const float* __restrict__ out_vth,
    float* __restrict__ out)
{
    const int blk  = blockIdx.x;
    const int tid  = threadIdx.x;
    const int warp = tid >> 5, lane = tid & 31;
    __shared__ float sh[4][16][4];
    __shared__ float4 cpbuf[4][STAGES * 4 * 32];   // 40KB
    float4* wbuf = cpbuf[warp];
    const uint32_t sb = (uint32_t)__cvta_generic_to_shared(wbuf);
    const uint64_t polS = pol_evict_first();   // one-shot streams (blk1, lmhead)
    const uint64_t polK = pol_evict_last();    // re-read weights (blk2)

    for (int i = blk * NTHR + tid; i < NBc * Bc * DNc; i += NBLK * NTHR) g_Vst[i] = 0.0f;
    for (int i = blk * NTHR + tid; i < NBc * Bc * Dc;  i += NBLK * NTHR) g_u[i]   = 0.0f;
    grid_sync();

    const int xI0 = warp * 64 + lane,  xI1 = xI0 + 32;
    const int vI0 = warp * 128 + lane, vI1 = vI0 + 32, vI2 = vI0 + 64, vI3 = vI0 + 96;

    int par = 0;
    for (int t = 0; t < Sc; ++t) {
        // ================= encoder: 2 rows/block =================
        {
            int j0 = blk * 2;
            const float* e0 = embed + (size_t)__ldg(tok + 0 * Sc + t) * Dc;
            const float* e1 = embed + (size_t)__ldg(tok + 1 * Sc + t) * Dc;
            const float* e2 = embed + (size_t)__ldg(tok + 2 * Sc + t) * Dc;
            const float* e3 = embed + (size_t)__ldg(tok + 3 * Sc + t) * Dc;
            float acc[8];
            ZERO(8);
            passN<2, 2>(encW + (size_t)j0 * Dc, Dc, e0, e1, e2, e3, warp, lane, acc);
            reduceN<8>(acc, sh[0], warp, lane);
            __syncthreads();
            if (tid < 8) {
                int r = tid >> 2, b = tid & 3;
                int j = j0 + r;
                float s = sh[0][tid][0] + sh[0][tid][1] + sh[0][tid][2] + sh[0][tid][3];
                float res = sigmf_(s + encb[j]);
#pragma unroll
                for (int k = 0; k < Kc; ++k) {
                    float bit = (res >= 0.5f) ? 1.0f : 0.0f;
                    g_frames[((size_t)k * Bc + b) * Dc + j] = bit;
                    res = (res - 0.5f * bit) * 2.0f;
                }
                g_decoded[b * Dc + j] = 0.0f;
            }
        }
        grid_sync();

        // ================= K frames x NB blocks =================
        for (int k = 0; k < Kc; ++k) {
            int xin = k;
            for (int i = 0; i < NBc; ++i) {
                // ---- blk1: 4 rows/block, ONE chained pipeline over 20 tiles ----
                {
                    size_t n0 = (size_t)blk * 4;
                    const float* x  = xsel_ptr(xin);
                    const float* Vi = g_Vst + ((size_t)par * NBc + i) * Bc * DNc;
                    float*       Vo = g_Vst + ((size_t)(par ^ 1) * NBc + i) * Bc * DNc;
                    const float* x0 = x;            const float* x1 = x + Dc;
                    const float* x2 = x + 2 * Dc;   const float* x3 = x + 3 * Dc;
                    const float* v0 = Vi;           const float* v1 = Vi + DNc;
                    const float* v2 = Vi + 2 * DNc; const float* v3 = Vi + 3 * DNc;
                    size_t rX = ((size_t)i * DNc + n0) * Dc;
                    size_t rV = ((size_t)i * DNc + n0) * DNc;
                    const float* WBX = WbX + rX; const float* WBV = WbV + rV;
                    const float* WAX = WaX + rX; const float* WAV = WaV + rV;
                    const float* WTX = WtX + rX; const float* WTV = WtV + rV;
                    const float* WIN = Win + rX;
                    float acc[16];

                    ZERO(16);
                    // prologue: tiles 0..2
                    ISS4(0, WBX, Dc,  xI0, polS);
                    ISS4(1, WBX, Dc,  xI1, polS);
                    ISS4(2, WBV, DNc, vI0, polS);
                    // steady state: issue T+3, consume T   (slot = T % 5)
                    ISS4(3, WBV, DNc, vI1, polS); CONS4(0, xI0, x0, x1, x2, x3);
                    ISS4(4, WBV, DNc, vI2, polS); CONS4(1, xI1, x0, x1, x2, x3);
                    ISS4(0, WBV, DNc, vI3, polS); CONS4(2, vI0, v0, v1, v2, v3);
                    ISS4(1, WAX, Dc,  xI0, polS); CONS4(3, vI1, v0, v1, v2, v3);
                    ISS4(2, WAX, Dc,  xI1, polS); CONS4(4, vI2, v0, v1, v2, v3);
                    ISS4(3, WAV, DNc, vI0, polS); CONS4(0, vI3, v0, v1, v2, v3);
                    reduceN<16>(acc, sh[0], warp, lane); ZERO(16);
                    ISS4(4, WAV, DNc, vI1, polS); CONS4(1, xI0, x0, x1, x2, x3);
                    ISS4(0, WAV, DNc, vI2, polS); CONS4(2, xI1, x0, x1, x2, x3);
                    ISS4(1, WAV, DNc, vI3, polS); CONS4(3, vI0, v0, v1, v2, v3);
                    ISS4(2, WTX, Dc,  xI0, polS); CONS4(4, vI1, v0, v1, v2, v3);
                    ISS4(3, WTX, Dc,  xI1, polS); CONS4(0, vI2, v0, v1, v2, v3);
                    ISS4(4, WTV, DNc, vI0, polS); CONS4(1, vI3, v0, v1, v2, v3);
                    reduceN<16>(acc, sh[1], warp, lane); ZERO(16);
                    ISS4(0, WTV, DNc, vI1, polS); CONS4(2, xI0, x0, x1, x2, x3);
                    ISS4(1, WTV, DNc, vI2, polS); CONS4(3, xI1, x0, x1, x2, x3);
                    ISS4(2, WTV, DNc, vI3, polS); CONS4(4, vI0, v0, v1, v2, v3);
                    ISS4(3, WIN, Dc,  xI0, polS); CONS4(0, vI1, v0, v1, v2, v3);
                    ISS4(4, WIN, Dc,  xI1, polS); CONS4(1, vI2, v0, v1, v2, v3);
                    ISS_NONE();                   CONS4(2, vI3, v0, v1, v2, v3);
                    reduceN<16>(acc, sh[2], warp, lane); ZERO(16);
                    ISS_NONE();                   CONS4(3, xI0, x0, x1, x2, x3);
                    ISS_NONE();                   CONS4(4, xI1, x0, x1, x2, x3);
                    reduceN<16>(acc, sh[3], warp, lane);

                    __syncthreads();
                    if (tid < 16) {
                        int r = tid >> 2, b = tid & 3;
                        size_t n = n0 + r;
                        float pB = sh[0][tid][0] + sh[0][tid][1] + sh[0][tid][2] + sh[0][tid][3];
                        float pA = sh[1][tid][0] + sh[1][tid][1] + sh[1][tid][2] + sh[1][tid][3];
                        float pT = sh[2][tid][0] + sh[2][tid][1] + sh[2][tid][2] + sh[2][tid][3];
                        float pI = sh[3][tid][0] + sh[3][tid][1] + sh[3][tid][2] + sh[3][tid][3];
                        float beta  = sigmf_(pB + b_beta[(size_t)i * DNc + n]);
                        float alpha = sigmf_(pA + b_alpha[(size_t)i * DNc + n]);
                        float vth   = 0.1f + softplusf_(pT + b_th[(size_t)i * DNc + n]);
                        float vold  = Vi[(size_t)b * DNc + n];
                        float vnew  = beta * vold + alpha * pI;
                        float spv   = ((vnew - vth) >= 0.0f) ? 1.0f : 0.0f;
                        Vo[(size_t)b * DNc + n]   = vnew - spv * vth;
                        g_sp[(size_t)b * DNc + n] = spv;
                    }
                }
                grid_sync();

                // ---- blk2: 2 rows/block, chained pipeline over 8 tiles ----
                {
                    int xo = Kc + (i & 1);
                    size_t j0 = (size_t)blk * 2;
                    const float* x = xsel_ptr(xin);
                    float* xout = g_xbuf[xo - Kc];
                    const float* x0 = x;           const float* x1 = x + Dc;
                    const float* x2 = x + 2 * Dc;  const float* x3 = x + 3 * Dc;
                    const float* s0 = g_sp;            const float* s1 = g_sp + DNc;
                    const float* s2 = g_sp + 2 * DNc;  const float* s3 = g_sp + 3 * DNc;
                    size_t rD = ((size_t)i * Dc + j0) * Dc;
                    size_t rN = ((size_t)i * Dc + j0) * DNc;
                    const float* WG = Wgate + rD;
                    const float* WS = Wskip + rD;
                    const float* WO = Wout + rN;
                    float acc[8];

                    ZERO(8);
                    // tiles: 0,1=gate(x it0,1) 2,3=skip(x) 4..7=out(s it0..3); slot=T%5
                    ISS2(0, WG, Dc,  xI0, polK);
                    ISS2(1, WG, Dc,  xI1, polK);
                    ISS2(2, WS, Dc,  xI0, polK);
                    ISS2(3, WS, Dc,  xI1, polK); CONS2(0, xI0, x0, x1, x2, x3);
                    ISS2(4, WO, DNc, vI0, polK); CONS2(1, xI1, x0, x1, x2, x3);
                    reduceN<8>(acc, sh[0], warp, lane); ZERO(8);
                    ISS2(0, WO, DNc, vI1, polK); CONS2(2, xI0, x0, x1, x2, x3);
                    ISS2(1, WO, DNc, vI2, polK); CONS2(3, xI1, x0, x1, x2, x3);
                    reduceN<8>(acc, sh[1], warp, lane); ZERO(8);
                    ISS2(2, WO, DNc, vI3, polK); CONS2(4, vI0, s0, s1, s2, s3);
                    ISS_NONE();                  CONS2(0, vI1, s0, s1, s2, s3);
                    ISS_NONE();                  CONS2(1, vI2, s0, s1, s2, s3);
                    ISS_NONE();                  CONS2(2, vI3, s0, s1, s2, s3);
                    reduceN<8>(acc, sh[2], warp, lane);

                    __syncthreads();
                    if (tid < 8) {
                        int r = tid >> 2, b = tid & 3;
                        size_t j = j0 + r;
                        float g  = sh[0][tid][0] + sh[0][tid][1] + sh[0][tid][2] + sh[0][tid][3];
                        float sk = sh[1][tid][0] + sh[1][tid][1] + sh[1][tid][2] + sh[1][tid][3];
                        float o  = sh[2][tid][0] + sh[2][tid][1] + sh[2][tid][2] + sh[2][tid][3];
                        float cur = sigmf_(g) * o + sk;
                        float tau = sigmf_(plif_w[i]);
                        float vt  = out_vth[i];
                        size_t ui = ((size_t)i * Bc + b) * Dc + j;
                        float uu = g_u[ui];
                        uu = uu + (cur - uu) * tau;
                        float so = ((uu - vt) >= 0.0f) ? 1.0f : 0.0f;
                        g_u[ui] = (1.0f - so) * uu;
                        xout[(size_t)b * Dc + j] = so;
                        if (i == NBc - 1) {
                            float wk = 1.0f / (float)(1 << (k + 1));
                            g_decoded[(size_t)b * Dc + j] += wk * so;
                        }
                    }
                    xin = xo;
                }
                grid_sync();
            }
            par ^= 1;
        }

        // ================= decoder: 2 rows/block =================
        {
            size_t j0 = (size_t)blk * 2;
            const float* d0 = g_decoded;           const float* d1 = g_decoded + Dc;
            const float* d2 = g_decoded + 2 * Dc;  const float* d3 = g_decoded + 3 * Dc;
            float acc[8];
            ZERO(8);
            passN<2, 2>(decW + j0 * Dc, Dc, d0, d1, d2, d3, warp, lane, acc);
            reduceN<8>(acc, sh[0], warp, lane);
            __syncthreads();
            if (tid < 8) {
                int r = tid >> 2, b = tid & 3;
                size_t j = j0 + r;
                float s = sh[0][tid][0] + sh[0][tid][1] + sh[0][tid][2] + sh[0][tid][3];
                g_hh[(size_t)b * Dc + j] = s + decb[j];
            }
        }
        grid_sync();

        // ================= RMSNorm (block 0 only) =================
        if (blk == 0) {
            __shared__ float srstd[Bc];
            if (warp < Bc) {
                float s = 0.0f;
                for (int j = lane; j < Dc; j += 32) {
                    float v = g_hh[warp * Dc + j];
                    s = fmaf(v, v, s);
                }
                s = warp_sum(s);
                if (lane == 0) srstd[warp] = 1.0f / sqrtf(s / (float)Dc + 1e-6f);
            }
            __syncthreads();
            for (int idx = tid; idx < Bc * Dc; idx += NTHR) {
                g_hh[idx] = g_hh[idx] * norm_w[idx & (Dc - 1)] * srstd[idx >> 10];
            }
        }
        grid_sync();

        // ================= LM head: chained over all iterations =================
        {
            const float* h0 = g_hh;           const float* h1 = g_hh + Dc;
            const float* h2 = g_hh + 2 * Dc;  const float* h3 = g_hh + 3 * Dc;
            // nit = 75 for blk<96 (last partial row group), else 74; uniform per block
            const int nit = ((size_t)74 * (NBLK * 4) + (size_t)blk * 4 < VOCABc) ? 75 : 74;
            const int TT  = nit * 2;
            float acc[16];
            ZERO(16);
            // prologue: tiles 0..2 (TT >= 148, always valid)
#pragma unroll
            for (int tau = 0; tau < PFD; ++tau) {
                int it2 = tau >> 1, sub = tau & 1;
                const float* wb2 = embed + ((size_t)it2 * (NBLK * 4) + (size_t)blk * 4) * Dc;
                ISS4(tau, wb2, Dc, xI0 + sub * 32, polS);
            }
            for (int tau = 0; tau < TT; ++tau) {
                int tf = tau + PFD;
                if (tf < TT) {
                    int it2 = tf >> 1, sub = tf & 1;
                    const float* wb2 = embed + ((size_t)it2 * (NBLK * 4) + (size_t)blk * 4) * Dc;
                    ISS4(tf % STAGES, wb2, Dc, xI0 + sub * 32, polS);
                } else {
                    ISS_NONE();
                }
                CONS4(tau % STAGES, xI0 + (tau & 1) * 32, h0, h1, h2, h3);
                if (tau & 1) {
                    reduceN<16>(acc, sh[0], warp, lane);
                    __syncthreads();
                    if (tid < 16) {
                        int r = tid >> 2, b = tid & 3;
                        size_t v0 = (size_t)(tau >> 1) * (NBLK * 4) + (size_t)blk * 4;
                        float s = sh[0][tid][0] + sh[0][tid][1] + sh[0][tid][2] + sh[0][tid][3];
                        out[((size_t)b * Sc + t) * VOCABc + v0 + r] = s;
                    }
                    __syncthreads();
                    ZERO(16);
                }
            }
        }
        // no grid_sync needed: the sync after enc(t+1) orders lmhead(t)
        // against the next writer of g_hh (dec at t+1).
    }
}

// ---------------- host driver: ONE graph node ----------------
extern "C" void kernel_launch(void* const* d_in, const int* in_sizes, int n_in,
                              void* d_out, int out_size)
{
    (void)in_sizes; (void)n_in; (void)out_size;
    snn_mono_kernel<<<NBLK, NTHR>>>(
        (const int*)d_in[0],  (const float*)d_in[1],  (const float*)d_in[2],
        (const float*)d_in[3], (const float*)d_in[4], (const float*)d_in[5],
        (const float*)d_in[6], (const float*)d_in[7], (const float*)d_in[8],
        (const float*)d_in[9], (const float*)d_in[10], (const float*)d_in[11],
        (const float*)d_in[12], (const float*)d_in[13], (const float*)d_in[14],
        (const float*)d_in[15], (const float*)d_in[16], (const float*)d_in[17],
        (const float*)d_in[18], (const float*)d_in[19], (const float*)d_in[20],
        (const float*)d_in[21], (float*)d_out);
}